// round 5
// baseline (speedup 1.0000x reference)
#include <cuda_runtime.h>
#include <math.h>

#define NMAX 500000
#define EMAX 8000000
#define CG_ITERS 20
#define TOL2 1e-8      // (CG_TOL)^2 against ||r||^2
#define SCAN_B 1024
#define EPT 16         // edges per thread in matvec
#define GPT 8          // edges per thread in grad

// ---------------- device scratch ----------------
__device__ int2   g_ew[EMAX];       // (src, w-as-int), dst-sorted
__device__ int    g_row[EMAX];      // dst (row) per sorted slot
__device__ float4 g_fn4[EMAX];      // face normal per sorted slot (w in .w unused)
__device__ int    g_cnt[NMAX];
__device__ int    g_off[NMAX + 1];
__device__ int    g_cur[NMAX];
__device__ int    g_spine[512];

__device__ float g_diag[NMAX];
__device__ float g_minv[NMAX];
__device__ float g_divacc[NMAX];
__device__ float g_phi[NMAX];
__device__ float g_r[NMAX];
__device__ float g_p[NMAX];
__device__ float g_ap[NMAX];
__device__ float g_grad[3 * NMAX];

__device__ double g_rz[CG_ITERS + 2];
__device__ double g_rr[CG_ITERS + 2];
__device__ double g_pap[CG_ITERS + 2];

// ---------------- reduction ----------------
__device__ __forceinline__ double blk_reduce_d(double v) {
    __shared__ double s[32];
    int lane = threadIdx.x & 31;
    int wp   = threadIdx.x >> 5;
    #pragma unroll
    for (int o = 16; o; o >>= 1) v += __shfl_down_sync(0xffffffffu, v, o);
    __syncthreads();
    if (lane == 0) s[wp] = v;
    __syncthreads();
    double r = 0.0;
    int nw = blockDim.x >> 5;
    if (threadIdx.x < nw) r = s[threadIdx.x];
    if (wp == 0) {
        #pragma unroll
        for (int o = 16; o; o >>= 1) r += __shfl_down_sync(0xffffffffu, r, o);
    }
    return r;
}

// ---------------- setup ----------------
__global__ void k_zero(int N) {
    int i = blockIdx.x * blockDim.x + threadIdx.x;
    if (i < 3 * N) g_grad[i] = 0.f;
    if (i < N) { g_cnt[i] = 0; g_diag[i] = 0.f; g_divacc[i] = 0.f; }
    if (i < CG_ITERS + 2) { g_rz[i] = 0.0; g_rr[i] = 0.0; g_pap[i] = 0.0; }
}

__global__ void k_hist(const int* __restrict__ dst, int E) {
    int e = blockIdx.x * blockDim.x + threadIdx.x;
    if (e < E) atomicAdd(&g_cnt[dst[e]], 1);
}

__global__ void k_scan1(int N) {
    __shared__ int sh[SCAN_B];
    int i = blockIdx.x * SCAN_B + threadIdx.x;
    int v = (i < N) ? g_cnt[i] : 0;
    sh[threadIdx.x] = v;
    __syncthreads();
    for (int o = 1; o < SCAN_B; o <<= 1) {
        int t = (threadIdx.x >= o) ? sh[threadIdx.x - o] : 0;
        __syncthreads();
        sh[threadIdx.x] += t;
        __syncthreads();
    }
    if (i < N) g_off[i] = sh[threadIdx.x] - v;
    if (threadIdx.x == SCAN_B - 1) g_spine[blockIdx.x] = sh[threadIdx.x];
}

__global__ void k_scan2(int nb) {
    __shared__ int sh[SCAN_B];
    int v = (threadIdx.x < nb) ? g_spine[threadIdx.x] : 0;
    sh[threadIdx.x] = v;
    __syncthreads();
    for (int o = 1; o < SCAN_B; o <<= 1) {
        int t = (threadIdx.x >= o) ? sh[threadIdx.x - o] : 0;
        __syncthreads();
        sh[threadIdx.x] += t;
        __syncthreads();
    }
    if (threadIdx.x < nb) g_spine[threadIdx.x] = sh[threadIdx.x] - v;
}

__global__ void k_scan3(int N, int E) {
    int i = blockIdx.x * blockDim.x + threadIdx.x;
    if (i < N) {
        int o = g_off[i] + g_spine[i / SCAN_B];
        g_off[i] = o;
        g_cur[i] = o;
    }
    if (i == 0) g_off[N] = E;
}

__global__ void k_scatter(const int* __restrict__ src,
                          const int* __restrict__ dst,
                          const float* __restrict__ u_hat,
                          const float* __restrict__ fn,
                          const float* __restrict__ fa,
                          const float* __restrict__ fd,
                          int E) {
    int e = blockIdx.x * blockDim.x + threadIdx.x;
    if (e >= E) return;
    int s = src[e], d = dst[e];
    float area = fa[e];
    float w = area / fmaxf(fd[e], 1e-8f);
    float n0 = fn[e * 3 + 0], n1 = fn[e * 3 + 1], n2 = fn[e * 3 + 2];
    float uf0 = 0.5f * (u_hat[s * 3 + 0] + u_hat[d * 3 + 0]);
    float uf1 = 0.5f * (u_hat[s * 3 + 1] + u_hat[d * 3 + 1]);
    float uf2 = 0.5f * (u_hat[s * 3 + 2] + u_hat[d * 3 + 2]);
    float flux = (uf0 * n0 + uf1 * n1 + uf2 * n2) * area;
    int pos = atomicAdd(&g_cur[d], 1);
    g_ew[pos] = make_int2(s, __float_as_int(w));
    g_row[pos] = d;
    g_fn4[pos] = make_float4(n0, n1, n2, 0.f);
    atomicAdd(&g_diag[d], w);
    atomicAdd(&g_divacc[d], flux);
}

// elementwise CG init; seed ap = diag*p0; accumulate rz[0], rr[0], pap[0](diag part)
__global__ void k_rowinit(const float* __restrict__ cv, int N) {
    int i = blockIdx.x * blockDim.x + threadIdx.x;
    double rz = 0.0, rr = 0.0, pp = 0.0;
    if (i < N) {
        float dgn = g_diag[i];
        float mi = 1.f / fmaxf(dgn, 1e-8f);
        float V = fmaxf(cv[i], 1e-12f);
        float b = g_divacc[i] / V;
        float z = mi * b;
        g_minv[i] = mi;
        g_phi[i] = 0.f;
        g_r[i] = b;
        g_p[i] = z;
        g_ap[i] = dgn * z;
        rz = (double)b * (double)z;
        rr = (double)b * (double)b;
        pp = (double)dgn * (double)z * (double)z;
    }
    double u = blk_reduce_d(rz);
    if (threadIdx.x == 0) atomicAdd(&g_rz[0], u);
    u = blk_reduce_d(rr);
    if (threadIdx.x == 0) atomicAdd(&g_rr[0], u);
    u = blk_reduce_d(pp);
    if (threadIdx.x == 0) atomicAdd(&g_pap[0], u);
}

// ---------------- CG: edge-centric off-diag matvec + fused pAp edge part ----------------
__global__ void __launch_bounds__(256) k_edge_mv(int E, int it) {
    int t = blockIdx.x * blockDim.x + threadIdx.x;
    int base = t * EPT;
    double papc = 0.0;
    if (base + EPT <= E) {
        const int4* ew4 = reinterpret_cast<const int4*>(g_ew);
        const int4* rw4 = reinterpret_cast<const int4*>(g_row);
        int t8 = t * 8, t4 = t * 4;
        int4 e0 = ew4[t8 + 0], e1 = ew4[t8 + 1], e2 = ew4[t8 + 2], e3 = ew4[t8 + 3];
        int4 e4 = ew4[t8 + 4], e5 = ew4[t8 + 5], e6 = ew4[t8 + 6], e7 = ew4[t8 + 7];
        int4 r0 = rw4[t4 + 0], r1 = rw4[t4 + 1], r2 = rw4[t4 + 2], r3 = rw4[t4 + 3];
        // 16 independent gathers
        float q0 = g_p[e0.x], q1 = g_p[e0.z], q2 = g_p[e1.x], q3 = g_p[e1.z];
        float q4 = g_p[e2.x], q5 = g_p[e2.z], q6 = g_p[e3.x], q7 = g_p[e3.z];
        float q8 = g_p[e4.x], q9 = g_p[e4.z], qa = g_p[e5.x], qb = g_p[e5.z];
        float qc = g_p[e6.x], qd = g_p[e6.z], qe = g_p[e7.x], qf = g_p[e7.z];
        float vals[16];
        vals[ 0] = __int_as_float(e0.y) * q0;  vals[ 1] = __int_as_float(e0.w) * q1;
        vals[ 2] = __int_as_float(e1.y) * q2;  vals[ 3] = __int_as_float(e1.w) * q3;
        vals[ 4] = __int_as_float(e2.y) * q4;  vals[ 5] = __int_as_float(e2.w) * q5;
        vals[ 6] = __int_as_float(e3.y) * q6;  vals[ 7] = __int_as_float(e3.w) * q7;
        vals[ 8] = __int_as_float(e4.y) * q8;  vals[ 9] = __int_as_float(e4.w) * q9;
        vals[10] = __int_as_float(e5.y) * qa;  vals[11] = __int_as_float(e5.w) * qb;
        vals[12] = __int_as_float(e6.y) * qc;  vals[13] = __int_as_float(e6.w) * qd;
        vals[14] = __int_as_float(e7.y) * qe;  vals[15] = __int_as_float(e7.w) * qf;
        int rows[16] = {r0.x, r0.y, r0.z, r0.w, r1.x, r1.y, r1.z, r1.w,
                        r2.x, r2.y, r2.z, r2.w, r3.x, r3.y, r3.z, r3.w};
        float acc = vals[0];
        int cur = rows[0];
        #pragma unroll
        for (int k = 1; k < EPT; k++) {
            if (rows[k] == cur) acc += vals[k];
            else {
                atomicAdd(&g_ap[cur], -acc);
                papc -= (double)acc * (double)g_p[cur];
                cur = rows[k]; acc = vals[k];
            }
        }
        atomicAdd(&g_ap[cur], -acc);
        papc -= (double)acc * (double)g_p[cur];
    } else if (base < E) {
        float acc = 0.f;
        int cur = -1;
        for (int k = base; k < E; k++) {
            int2 ew = g_ew[k];
            int rw = g_row[k];
            float v = __int_as_float(ew.y) * g_p[ew.x];
            if (rw == cur) acc += v;
            else {
                if (cur >= 0) { atomicAdd(&g_ap[cur], -acc); papc -= (double)acc * (double)g_p[cur]; }
                cur = rw; acc = v;
            }
        }
        if (cur >= 0) { atomicAdd(&g_ap[cur], -acc); papc -= (double)acc * (double)g_p[cur]; }
    }
    double u = blk_reduce_d(papc);
    if (threadIdx.x == 0) atomicAdd(&g_pap[it], u);
}

// if active: phi += a p; r -= a ap; acc rz_new, rr_new
__global__ void k_upd_phi_r(int N, int it) {
    int i = blockIdx.x * blockDim.x + threadIdx.x;
    bool act = (g_rr[it] >= TOL2);
    float alpha = (float)(g_rz[it] / (g_pap[it] + 1e-12));
    double rzc = 0.0, rrc = 0.0;
    int i4 = i * 4;
    if (act && i4 < N) {
        if (i4 + 3 < N) {
            float4 p  = *reinterpret_cast<const float4*>(&g_p[i4]);
            float4 ap = *reinterpret_cast<const float4*>(&g_ap[i4]);
            float4 r  = *reinterpret_cast<const float4*>(&g_r[i4]);
            float4 mi = *reinterpret_cast<const float4*>(&g_minv[i4]);
            float4 ph = *reinterpret_cast<const float4*>(&g_phi[i4]);
            ph.x += alpha * p.x; ph.y += alpha * p.y;
            ph.z += alpha * p.z; ph.w += alpha * p.w;
            r.x -= alpha * ap.x; r.y -= alpha * ap.y;
            r.z -= alpha * ap.z; r.w -= alpha * ap.w;
            *reinterpret_cast<float4*>(&g_phi[i4]) = ph;
            *reinterpret_cast<float4*>(&g_r[i4]) = r;
            rzc = (double)r.x * (mi.x * r.x) + (double)r.y * (mi.y * r.y)
                + (double)r.z * (mi.z * r.z) + (double)r.w * (mi.w * r.w);
            rrc = (double)r.x * r.x + (double)r.y * r.y
                + (double)r.z * r.z + (double)r.w * r.w;
        } else {
            for (int j = i4; j < N; j++) {
                g_phi[j] += alpha * g_p[j];
                float rn = g_r[j] - alpha * g_ap[j];
                g_r[j] = rn;
                rzc += (double)rn * (g_minv[j] * rn);
                rrc += (double)rn * rn;
            }
        }
    }
    double u = blk_reduce_d(rzc);
    if (threadIdx.x == 0) atomicAdd(&g_rz[it + 1], u);
    u = blk_reduce_d(rrc);
    if (threadIdx.x == 0) atomicAdd(&g_rr[it + 1], u);
}

// if active: p = minv*r + beta*p; reseed ap = diag*p; acc pap[it+1] diag part
__global__ void k_upd_p(int N, int it) {
    int i = blockIdx.x * blockDim.x + threadIdx.x;
    int i4 = i * 4;
    bool act = (g_rr[it] >= TOL2);
    float beta = (float)(g_rz[it + 1] / (g_rz[it] + 1e-12));
    double pp = 0.0;
    if (i4 + 3 < N) {
        float4 p  = *reinterpret_cast<const float4*>(&g_p[i4]);
        float4 d  = *reinterpret_cast<const float4*>(&g_diag[i4]);
        if (act) {
            float4 r  = *reinterpret_cast<const float4*>(&g_r[i4]);
            float4 mi = *reinterpret_cast<const float4*>(&g_minv[i4]);
            p.x = mi.x * r.x + beta * p.x;
            p.y = mi.y * r.y + beta * p.y;
            p.z = mi.z * r.z + beta * p.z;
            p.w = mi.w * r.w + beta * p.w;
            *reinterpret_cast<float4*>(&g_p[i4]) = p;
        }
        float4 ap;
        ap.x = d.x * p.x; ap.y = d.y * p.y; ap.z = d.z * p.z; ap.w = d.w * p.w;
        *reinterpret_cast<float4*>(&g_ap[i4]) = ap;
        pp = (double)ap.x * p.x + (double)ap.y * p.y
           + (double)ap.z * p.z + (double)ap.w * p.w;
    } else if (i4 < N) {
        for (int j = i4; j < N; j++) {
            float p = g_p[j];
            if (act) { p = g_minv[j] * g_r[j] + beta * p; g_p[j] = p; }
            float ap = g_diag[j] * p;
            g_ap[j] = ap;
            pp += (double)ap * p;
        }
    }
    double u = blk_reduce_d(pp);
    if (threadIdx.x == 0) atomicAdd(&g_pap[it + 1], u);
}

// ---------------- correction: run-length gradient over CSR ----------------
__global__ void k_grad_csr(int E) {
    int t = blockIdx.x * blockDim.x + threadIdx.x;
    int base = t * GPT;
    if (base >= E) return;
    int end = min(base + GPT, E);
    float gx = 0.f, gy = 0.f, gz = 0.f;
    int cur = -1;
    for (int k = base; k < end; k++) {
        int2 ew = g_ew[k];
        int rw = g_row[k];
        float4 n = g_fn4[k];
        float tt = __int_as_float(ew.y) * g_phi[ew.x];
        if (rw != cur) {
            if (cur >= 0) {
                atomicAdd(&g_grad[cur * 3 + 0], gx);
                atomicAdd(&g_grad[cur * 3 + 1], gy);
                atomicAdd(&g_grad[cur * 3 + 2], gz);
            }
            cur = rw; gx = 0.f; gy = 0.f; gz = 0.f;
        }
        gx += tt * n.x; gy += tt * n.y; gz += tt * n.z;
    }
    if (cur >= 0) {
        atomicAdd(&g_grad[cur * 3 + 0], gx);
        atomicAdd(&g_grad[cur * 3 + 1], gy);
        atomicAdd(&g_grad[cur * 3 + 2], gz);
    }
}

__global__ void k_final(const float* __restrict__ u_hat,
                        const float* __restrict__ cv,
                        float* __restrict__ out, int N) {
    int i = blockIdx.x * blockDim.x + threadIdx.x;
    if (i >= N) return;
    float Vi = 1.f / fmaxf(cv[i], 1e-12f);
    out[i * 3 + 0] = u_hat[i * 3 + 0] - g_grad[i * 3 + 0] * Vi;
    out[i * 3 + 1] = u_hat[i * 3 + 1] - g_grad[i * 3 + 1] * Vi;
    out[i * 3 + 2] = u_hat[i * 3 + 2] - g_grad[i * 3 + 2] * Vi;
    out[3 * N + i] = g_phi[i];
}

// ---------------- launch ----------------
extern "C" void kernel_launch(void* const* d_in, const int* in_sizes, int n_in,
                              void* d_out, int out_size) {
    const float* u_hat = (const float*)d_in[0];
    const int*   ei    = (const int*)  d_in[1];
    const float* fn    = (const float*)d_in[2];
    const float* fa    = (const float*)d_in[3];
    const float* fd    = (const float*)d_in[4];
    const float* cv    = (const float*)d_in[5];
    float* out = (float*)d_out;

    int N = in_sizes[5];
    int E = in_sizes[3];
    const int* src = ei;
    const int* dst = ei + E;

    const int B = 256;
    int gridE   = (E + B - 1) / B;
    int gridN   = (N + B - 1) / B;
    int grid3N  = (3 * N + B - 1) / B;
    int gridMV  = ((E + EPT - 1) / EPT + B - 1) / B;
    int gridG   = ((E + GPT - 1) / GPT + B - 1) / B;
    int gridN4  = ((N + 3) / 4 + B - 1) / B;
    int nScanBlocks = (N + SCAN_B - 1) / SCAN_B;

    k_zero<<<grid3N, B>>>(N);
    k_hist<<<gridE, B>>>(dst, E);
    k_scan1<<<nScanBlocks, SCAN_B>>>(N);
    k_scan2<<<1, SCAN_B>>>(nScanBlocks);
    k_scan3<<<gridN, B>>>(N, E);
    k_scatter<<<gridE, B>>>(src, dst, u_hat, fn, fa, fd, E);
    k_rowinit<<<gridN, B>>>(cv, N);

    for (int it = 0; it < CG_ITERS; ++it) {
        k_edge_mv<<<gridMV, B>>>(E, it);
        k_upd_phi_r<<<gridN4, B>>>(N, it);
        k_upd_p<<<gridN4, B>>>(N, it);
    }

    k_grad_csr<<<gridG, B>>>(E);
    k_final<<<gridN, B>>>(u_hat, cv, out, N);
}

// round 6
// speedup vs baseline: 1.4281x; 1.4281x over previous
#include <cuda_runtime.h>
#include <math.h>

#define NMAX 500000
#define EMAX 8000000
#define CG_ITERS 20
#define TOL2 1e-8      // (CG_TOL)^2 against ||r||^2
#define SCAN_B 1024
#define EPT 16         // edges per thread in matvec (floats only, no fp64)

// ---------------- device scratch ----------------
__device__ int2  g_ew[EMAX];        // (src, w-as-int), dst-sorted
__device__ int   g_row[EMAX];       // dst (row) per sorted slot (filled from CSR)
__device__ int   g_cnt[NMAX];
__device__ int   g_off[NMAX + 1];
__device__ int   g_cur[NMAX];
__device__ int   g_spine[512];

__device__ float g_diag[NMAX];
__device__ float g_minv[NMAX];
__device__ float g_divacc[NMAX];
__device__ float g_phi[NMAX];
__device__ float g_r[NMAX];
__device__ float g_p[NMAX];
__device__ float g_ap[NMAX];
__device__ float g_grad[3 * NMAX];

__device__ double g_rz[CG_ITERS + 2];
__device__ double g_rr[CG_ITERS + 2];
__device__ double g_pap[CG_ITERS + 1];

// ---------------- reduction ----------------
__device__ __forceinline__ double blk_reduce_d(double v) {
    __shared__ double s[32];
    int lane = threadIdx.x & 31;
    int wp   = threadIdx.x >> 5;
    #pragma unroll
    for (int o = 16; o; o >>= 1) v += __shfl_down_sync(0xffffffffu, v, o);
    __syncthreads();
    if (lane == 0) s[wp] = v;
    __syncthreads();
    double r = 0.0;
    int nw = blockDim.x >> 5;
    if (threadIdx.x < nw) r = s[threadIdx.x];
    if (wp == 0) {
        #pragma unroll
        for (int o = 16; o; o >>= 1) r += __shfl_down_sync(0xffffffffu, r, o);
    }
    return r;
}

// ---------------- setup ----------------
__global__ void k_zero(int N) {
    int i = blockIdx.x * blockDim.x + threadIdx.x;
    if (i < 3 * N) g_grad[i] = 0.f;
    if (i < N) { g_cnt[i] = 0; g_diag[i] = 0.f; g_divacc[i] = 0.f; }
    if (i < CG_ITERS + 2) { g_rz[i] = 0.0; g_rr[i] = 0.0; }
    if (i < CG_ITERS + 1) g_pap[i] = 0.0;
}

__global__ void k_hist(const int* __restrict__ dst, int E) {
    int e = blockIdx.x * blockDim.x + threadIdx.x;
    if (e < E) atomicAdd(&g_cnt[dst[e]], 1);
}

__global__ void k_scan1(int N) {
    __shared__ int sh[SCAN_B];
    int i = blockIdx.x * SCAN_B + threadIdx.x;
    int v = (i < N) ? g_cnt[i] : 0;
    sh[threadIdx.x] = v;
    __syncthreads();
    for (int o = 1; o < SCAN_B; o <<= 1) {
        int t = (threadIdx.x >= o) ? sh[threadIdx.x - o] : 0;
        __syncthreads();
        sh[threadIdx.x] += t;
        __syncthreads();
    }
    if (i < N) g_off[i] = sh[threadIdx.x] - v;
    if (threadIdx.x == SCAN_B - 1) g_spine[blockIdx.x] = sh[threadIdx.x];
}

__global__ void k_scan2(int nb) {
    __shared__ int sh[SCAN_B];
    int v = (threadIdx.x < nb) ? g_spine[threadIdx.x] : 0;
    sh[threadIdx.x] = v;
    __syncthreads();
    for (int o = 1; o < SCAN_B; o <<= 1) {
        int t = (threadIdx.x >= o) ? sh[threadIdx.x - o] : 0;
        __syncthreads();
        sh[threadIdx.x] += t;
        __syncthreads();
    }
    if (threadIdx.x < nb) g_spine[threadIdx.x] = sh[threadIdx.x] - v;
}

__global__ void k_scan3(int N, int E) {
    int i = blockIdx.x * blockDim.x + threadIdx.x;
    if (i < N) {
        int o = g_off[i] + g_spine[i / SCAN_B];
        g_off[i] = o;
        g_cur[i] = o;
    }
    if (i == 0) g_off[N] = E;
}

// fill g_row from CSR offsets (sequential writes, replaces random scatter writes)
__global__ void k_fillrow(int N) {
    int i = blockIdx.x * blockDim.x + threadIdx.x;
    if (i >= N) return;
    int s = g_off[i], e = g_off[i + 1];
    for (int k = s; k < e; k++) g_row[k] = i;
}

__global__ void k_scatter(const int* __restrict__ src,
                          const int* __restrict__ dst,
                          const float* __restrict__ u_hat,
                          const float* __restrict__ fn,
                          const float* __restrict__ fa,
                          const float* __restrict__ fd,
                          int E) {
    int e = blockIdx.x * blockDim.x + threadIdx.x;
    if (e >= E) return;
    int s = src[e], d = dst[e];
    float area = fa[e];
    float w = area / fmaxf(fd[e], 1e-8f);
    float n0 = fn[e * 3 + 0], n1 = fn[e * 3 + 1], n2 = fn[e * 3 + 2];
    float uf0 = 0.5f * (u_hat[s * 3 + 0] + u_hat[d * 3 + 0]);
    float uf1 = 0.5f * (u_hat[s * 3 + 1] + u_hat[d * 3 + 1]);
    float uf2 = 0.5f * (u_hat[s * 3 + 2] + u_hat[d * 3 + 2]);
    float flux = (uf0 * n0 + uf1 * n1 + uf2 * n2) * area;
    int pos = atomicAdd(&g_cur[d], 1);
    g_ew[pos] = make_int2(s, __float_as_int(w));
    atomicAdd(&g_diag[d], w);
    atomicAdd(&g_divacc[d], flux);
}

// elementwise CG init; seed ap = diag*p0; accumulate rz[0], rr[0]
__global__ void k_rowinit(const float* __restrict__ cv, int N) {
    int i = blockIdx.x * blockDim.x + threadIdx.x;
    double rz = 0.0, rr = 0.0;
    if (i < N) {
        float dgn = g_diag[i];
        float mi = 1.f / fmaxf(dgn, 1e-8f);
        float V = fmaxf(cv[i], 1e-12f);
        float b = g_divacc[i] / V;
        float z = mi * b;
        g_minv[i] = mi;
        g_phi[i] = 0.f;
        g_r[i] = b;
        g_p[i] = z;
        g_ap[i] = dgn * z;           // diag part of A*p0
        rz = (double)b * (double)z;
        rr = (double)b * (double)b;
    }
    double u = blk_reduce_d(rz);
    if (threadIdx.x == 0) atomicAdd(&g_rz[0], u);
    u = blk_reduce_d(rr);
    if (threadIdx.x == 0) atomicAdd(&g_rr[0], u);
}

// ---------------- CG: edge-centric off-diagonal matvec (floats only) ----------------
__global__ void __launch_bounds__(256) k_edge_mv(int E) {
    int t = blockIdx.x * blockDim.x + threadIdx.x;
    int base = t * EPT;
    if (base >= E) return;
    if (base + EPT <= E) {
        const int4* ew4 = reinterpret_cast<const int4*>(g_ew);
        const int4* rw4 = reinterpret_cast<const int4*>(g_row);
        int t8 = t * 8, t4 = t * 4;
        int4 e0 = ew4[t8 + 0], e1 = ew4[t8 + 1], e2 = ew4[t8 + 2], e3 = ew4[t8 + 3];
        int4 e4 = ew4[t8 + 4], e5 = ew4[t8 + 5], e6 = ew4[t8 + 6], e7 = ew4[t8 + 7];
        int4 r0 = rw4[t4 + 0], r1 = rw4[t4 + 1], r2 = rw4[t4 + 2], r3 = rw4[t4 + 3];
        // 16 independent gathers
        float q0 = g_p[e0.x], q1 = g_p[e0.z], q2 = g_p[e1.x], q3 = g_p[e1.z];
        float q4 = g_p[e2.x], q5 = g_p[e2.z], q6 = g_p[e3.x], q7 = g_p[e3.z];
        float q8 = g_p[e4.x], q9 = g_p[e4.z], qa = g_p[e5.x], qb = g_p[e5.z];
        float qc = g_p[e6.x], qd = g_p[e6.z], qe = g_p[e7.x], qf = g_p[e7.z];
        float vals[16];
        vals[ 0] = __int_as_float(e0.y) * q0;  vals[ 1] = __int_as_float(e0.w) * q1;
        vals[ 2] = __int_as_float(e1.y) * q2;  vals[ 3] = __int_as_float(e1.w) * q3;
        vals[ 4] = __int_as_float(e2.y) * q4;  vals[ 5] = __int_as_float(e2.w) * q5;
        vals[ 6] = __int_as_float(e3.y) * q6;  vals[ 7] = __int_as_float(e3.w) * q7;
        vals[ 8] = __int_as_float(e4.y) * q8;  vals[ 9] = __int_as_float(e4.w) * q9;
        vals[10] = __int_as_float(e5.y) * qa;  vals[11] = __int_as_float(e5.w) * qb;
        vals[12] = __int_as_float(e6.y) * qc;  vals[13] = __int_as_float(e6.w) * qd;
        vals[14] = __int_as_float(e7.y) * qe;  vals[15] = __int_as_float(e7.w) * qf;
        int rows[16] = {r0.x, r0.y, r0.z, r0.w, r1.x, r1.y, r1.z, r1.w,
                        r2.x, r2.y, r2.z, r2.w, r3.x, r3.y, r3.z, r3.w};
        float acc = vals[0];
        int cur = rows[0];
        #pragma unroll
        for (int k = 1; k < EPT; k++) {
            if (rows[k] == cur) acc += vals[k];
            else { atomicAdd(&g_ap[cur], -acc); cur = rows[k]; acc = vals[k]; }
        }
        atomicAdd(&g_ap[cur], -acc);
    } else {
        float acc = 0.f;
        int cur = -1;
        for (int k = base; k < E; k++) {
            int2 ew = g_ew[k];
            int rw = g_row[k];
            float v = __int_as_float(ew.y) * g_p[ew.x];
            if (rw == cur) acc += v;
            else { if (cur >= 0) atomicAdd(&g_ap[cur], -acc); cur = rw; acc = v; }
        }
        if (cur >= 0) atomicAdd(&g_ap[cur], -acc);
    }
}

// pAp[it] = sum p_i * ap_i  (ap now complete)
__global__ void k_pap(int N, int it) {
    int i = blockIdx.x * blockDim.x + threadIdx.x;
    double c = 0.0;
    int i4 = i * 4;
    if (i4 + 3 < N) {
        float4 p = *reinterpret_cast<const float4*>(&g_p[i4]);
        float4 a = *reinterpret_cast<const float4*>(&g_ap[i4]);
        c = (double)p.x * a.x + (double)p.y * a.y + (double)p.z * a.z + (double)p.w * a.w;
    } else {
        for (int j = i4; j < N; j++) c += (double)g_p[j] * (double)g_ap[j];
    }
    double u = blk_reduce_d(c);
    if (threadIdx.x == 0) atomicAdd(&g_pap[it], u);
}

// if active: phi += a p; r -= a ap; acc rz_new (r*minv*r), rr_new
__global__ void k_upd_phi_r(int N, int it) {
    int i = blockIdx.x * blockDim.x + threadIdx.x;
    bool act = (g_rr[it] >= TOL2);
    float alpha = (float)(g_rz[it] / (g_pap[it] + 1e-12));
    double rzc = 0.0, rrc = 0.0;
    int i4 = i * 4;
    if (act && i4 < N) {
        if (i4 + 3 < N) {
            float4 p  = *reinterpret_cast<const float4*>(&g_p[i4]);
            float4 ap = *reinterpret_cast<const float4*>(&g_ap[i4]);
            float4 r  = *reinterpret_cast<const float4*>(&g_r[i4]);
            float4 mi = *reinterpret_cast<const float4*>(&g_minv[i4]);
            float4 ph = *reinterpret_cast<const float4*>(&g_phi[i4]);
            ph.x += alpha * p.x; ph.y += alpha * p.y;
            ph.z += alpha * p.z; ph.w += alpha * p.w;
            r.x -= alpha * ap.x; r.y -= alpha * ap.y;
            r.z -= alpha * ap.z; r.w -= alpha * ap.w;
            *reinterpret_cast<float4*>(&g_phi[i4]) = ph;
            *reinterpret_cast<float4*>(&g_r[i4]) = r;
            rzc = (double)r.x * (mi.x * r.x) + (double)r.y * (mi.y * r.y)
                + (double)r.z * (mi.z * r.z) + (double)r.w * (mi.w * r.w);
            rrc = (double)r.x * r.x + (double)r.y * r.y
                + (double)r.z * r.z + (double)r.w * r.w;
        } else {
            for (int j = i4; j < N; j++) {
                g_phi[j] += alpha * g_p[j];
                float rn = g_r[j] - alpha * g_ap[j];
                g_r[j] = rn;
                rzc += (double)rn * (g_minv[j] * rn);
                rrc += (double)rn * rn;
            }
        }
    }
    double u = blk_reduce_d(rzc);
    if (threadIdx.x == 0) atomicAdd(&g_rz[it + 1], u);
    u = blk_reduce_d(rrc);
    if (threadIdx.x == 0) atomicAdd(&g_rr[it + 1], u);
}

// if active: p = minv*r + beta*p; always reseed ap = diag*p (for next matvec)
__global__ void k_upd_p(int N, int it) {
    int i = blockIdx.x * blockDim.x + threadIdx.x;
    int i4 = i * 4;
    if (i4 >= N) return;
    bool act = (g_rr[it] >= TOL2);
    float beta = (float)(g_rz[it + 1] / (g_rz[it] + 1e-12));
    if (i4 + 3 < N) {
        float4 p  = *reinterpret_cast<const float4*>(&g_p[i4]);
        float4 d  = *reinterpret_cast<const float4*>(&g_diag[i4]);
        if (act) {
            float4 r  = *reinterpret_cast<const float4*>(&g_r[i4]);
            float4 mi = *reinterpret_cast<const float4*>(&g_minv[i4]);
            p.x = mi.x * r.x + beta * p.x;
            p.y = mi.y * r.y + beta * p.y;
            p.z = mi.z * r.z + beta * p.z;
            p.w = mi.w * r.w + beta * p.w;
            *reinterpret_cast<float4*>(&g_p[i4]) = p;
        }
        float4 ap;
        ap.x = d.x * p.x; ap.y = d.y * p.y; ap.z = d.z * p.z; ap.w = d.w * p.w;
        *reinterpret_cast<float4*>(&g_ap[i4]) = ap;
    } else {
        for (int j = i4; j < N; j++) {
            float p = g_p[j];
            if (act) { p = g_minv[j] * g_r[j] + beta * p; g_p[j] = p; }
            g_ap[j] = g_diag[j] * p;
        }
    }
}

// ---------------- correction ----------------
__global__ void k_grad(const int* __restrict__ src,
                       const int* __restrict__ dst,
                       const float* __restrict__ fn,
                       const float* __restrict__ fa,
                       const float* __restrict__ fd,
                       int E) {
    int e = blockIdx.x * blockDim.x + threadIdx.x;
    if (e >= E) return;
    int s = src[e], d = dst[e];
    float w = fa[e] / fmaxf(fd[e], 1e-8f);
    float t = w * g_phi[s];
    atomicAdd(&g_grad[d * 3 + 0], t * fn[e * 3 + 0]);
    atomicAdd(&g_grad[d * 3 + 1], t * fn[e * 3 + 1]);
    atomicAdd(&g_grad[d * 3 + 2], t * fn[e * 3 + 2]);
}

__global__ void k_final(const float* __restrict__ u_hat,
                        const float* __restrict__ cv,
                        float* __restrict__ out, int N) {
    int i = blockIdx.x * blockDim.x + threadIdx.x;
    if (i >= N) return;
    float Vi = 1.f / fmaxf(cv[i], 1e-12f);
    out[i * 3 + 0] = u_hat[i * 3 + 0] - g_grad[i * 3 + 0] * Vi;
    out[i * 3 + 1] = u_hat[i * 3 + 1] - g_grad[i * 3 + 1] * Vi;
    out[i * 3 + 2] = u_hat[i * 3 + 2] - g_grad[i * 3 + 2] * Vi;
    out[3 * N + i] = g_phi[i];
}

// ---------------- launch ----------------
extern "C" void kernel_launch(void* const* d_in, const int* in_sizes, int n_in,
                              void* d_out, int out_size) {
    const float* u_hat = (const float*)d_in[0];
    const int*   ei    = (const int*)  d_in[1];
    const float* fn    = (const float*)d_in[2];
    const float* fa    = (const float*)d_in[3];
    const float* fd    = (const float*)d_in[4];
    const float* cv    = (const float*)d_in[5];
    float* out = (float*)d_out;

    int N = in_sizes[5];
    int E = in_sizes[3];
    const int* src = ei;
    const int* dst = ei + E;

    const int B = 256;
    int gridE   = (E + B - 1) / B;
    int gridN   = (N + B - 1) / B;
    int grid3N  = (3 * N + B - 1) / B;
    int gridMV  = ((E + EPT - 1) / EPT + B - 1) / B;
    int gridN4  = ((N + 3) / 4 + B - 1) / B;
    int nScanBlocks = (N + SCAN_B - 1) / SCAN_B;

    k_zero<<<grid3N, B>>>(N);
    k_hist<<<gridE, B>>>(dst, E);
    k_scan1<<<nScanBlocks, SCAN_B>>>(N);
    k_scan2<<<1, SCAN_B>>>(nScanBlocks);
    k_scan3<<<gridN, B>>>(N, E);
    k_fillrow<<<gridN, B>>>(N);
    k_scatter<<<gridE, B>>>(src, dst, u_hat, fn, fa, fd, E);
    k_rowinit<<<gridN, B>>>(cv, N);

    for (int it = 0; it < CG_ITERS; ++it) {
        k_edge_mv<<<gridMV, B>>>(E);
        k_pap<<<gridN4, B>>>(N, it);
        k_upd_phi_r<<<gridN4, B>>>(N, it);
        k_upd_p<<<gridN4, B>>>(N, it);
    }

    k_grad<<<gridE, B>>>(src, dst, fn, fa, fd, E);
    k_final<<<gridN, B>>>(u_hat, cv, out, N);
}

// round 7
// speedup vs baseline: 1.5807x; 1.1069x over previous
#include <cuda_runtime.h>
#include <math.h>

#define NMAX 500000
#define EMAX 8000000
#define CG_ITERS 20
#define TOL2 1e-8      // (CG_TOL)^2 against ||r||^2
#define SCAN_B 1024
#define EPT 8          // edges per thread in matvec

// ---------------- device scratch ----------------
__device__ int2  g_ew[EMAX];            // (src, w-as-int), dst-sorted
__device__ int   g_row[EMAX];           // build temp: dst per sorted slot
__device__ int   g_trow[EMAX / 8 + 2];  // base row per 8-edge chunk
__device__ uint2 g_rowd2[EMAX / 8 + 2]; // 8x 8-bit row deltas per chunk
__device__ int   g_cnt[NMAX];
__device__ int   g_off[NMAX + 1];
__device__ int   g_cur[NMAX];
__device__ int   g_spine[512];

__device__ float g_diag[NMAX];
__device__ float g_minv[NMAX];
__device__ float g_divacc[NMAX];
__device__ float g_phi[NMAX];
__device__ float g_r[NMAX];
__device__ float g_p[NMAX];
__device__ float g_ap[NMAX];
__device__ float g_grad[3 * NMAX];

__device__ double g_rz[CG_ITERS + 2];
__device__ double g_rr[CG_ITERS + 2];
__device__ double g_pap[CG_ITERS + 1];

// ---------------- reduction ----------------
__device__ __forceinline__ double blk_reduce_d(double v) {
    __shared__ double s[32];
    int lane = threadIdx.x & 31;
    int wp   = threadIdx.x >> 5;
    #pragma unroll
    for (int o = 16; o; o >>= 1) v += __shfl_down_sync(0xffffffffu, v, o);
    __syncthreads();
    if (lane == 0) s[wp] = v;
    __syncthreads();
    double r = 0.0;
    int nw = blockDim.x >> 5;
    if (threadIdx.x < nw) r = s[threadIdx.x];
    if (wp == 0) {
        #pragma unroll
        for (int o = 16; o; o >>= 1) r += __shfl_down_sync(0xffffffffu, r, o);
    }
    return r;
}

// ---------------- setup ----------------
__global__ void k_zero(int N) {
    int i = blockIdx.x * blockDim.x + threadIdx.x;
    if (i < 3 * N) g_grad[i] = 0.f;
    if (i < N) { g_cnt[i] = 0; g_diag[i] = 0.f; g_divacc[i] = 0.f; }
    if (i < CG_ITERS + 2) { g_rz[i] = 0.0; g_rr[i] = 0.0; }
    if (i < CG_ITERS + 1) g_pap[i] = 0.0;
}

__global__ void k_hist(const int* __restrict__ dst, int E) {
    int e = blockIdx.x * blockDim.x + threadIdx.x;
    if (e < E) atomicAdd(&g_cnt[dst[e]], 1);
}

__global__ void k_scan1(int N) {
    __shared__ int sh[SCAN_B];
    int i = blockIdx.x * SCAN_B + threadIdx.x;
    int v = (i < N) ? g_cnt[i] : 0;
    sh[threadIdx.x] = v;
    __syncthreads();
    for (int o = 1; o < SCAN_B; o <<= 1) {
        int t = (threadIdx.x >= o) ? sh[threadIdx.x - o] : 0;
        __syncthreads();
        sh[threadIdx.x] += t;
        __syncthreads();
    }
    if (i < N) g_off[i] = sh[threadIdx.x] - v;
    if (threadIdx.x == SCAN_B - 1) g_spine[blockIdx.x] = sh[threadIdx.x];
}

__global__ void k_scan2(int nb) {
    __shared__ int sh[SCAN_B];
    int v = (threadIdx.x < nb) ? g_spine[threadIdx.x] : 0;
    sh[threadIdx.x] = v;
    __syncthreads();
    for (int o = 1; o < SCAN_B; o <<= 1) {
        int t = (threadIdx.x >= o) ? sh[threadIdx.x - o] : 0;
        __syncthreads();
        sh[threadIdx.x] += t;
        __syncthreads();
    }
    if (threadIdx.x < nb) g_spine[threadIdx.x] = sh[threadIdx.x] - v;
}

__global__ void k_scan3(int N, int E) {
    int i = blockIdx.x * blockDim.x + threadIdx.x;
    if (i < N) {
        int o = g_off[i] + g_spine[i / SCAN_B];
        g_off[i] = o;
        g_cur[i] = o;
    }
    if (i == 0) g_off[N] = E;
}

// fill g_row build-temp from CSR offsets (coalesced-ish sequential writes)
__global__ void k_fillrow(int N) {
    int i = blockIdx.x * blockDim.x + threadIdx.x;
    if (i >= N) return;
    int s = g_off[i], e = g_off[i + 1];
    for (int k = s; k < e; k++) g_row[k] = i;
}

// pack per-chunk base row + 8x byte deltas (edge-centric, coalesced)
__global__ void k_packrow(int E) {
    int t = blockIdx.x * blockDim.x + threadIdx.x;
    int base = t * 8;
    if (base >= E) return;
    if (base + 8 <= E) {
        const int4* rw4 = reinterpret_cast<const int4*>(g_row);
        int4 r0 = rw4[t * 2], r1 = rw4[t * 2 + 1];
        int b = r0.x;
        g_trow[t] = b;
        unsigned d0 = (unsigned)(r0.x - b), d1 = (unsigned)(r0.y - b);
        unsigned d2 = (unsigned)(r0.z - b), d3 = (unsigned)(r0.w - b);
        unsigned d4 = (unsigned)(r1.x - b), d5 = (unsigned)(r1.y - b);
        unsigned d6 = (unsigned)(r1.z - b), d7 = (unsigned)(r1.w - b);
        uint2 packed;
        packed.x = d0 | (d1 << 8) | (d2 << 16) | (d3 << 24);
        packed.y = d4 | (d5 << 8) | (d6 << 16) | (d7 << 24);
        g_rowd2[t] = packed;
    } else {
        int b = g_row[base];
        g_trow[t] = b;
        unsigned char* rb = reinterpret_cast<unsigned char*>(g_rowd2);
        for (int k = base; k < E; k++) rb[k] = (unsigned char)(g_row[k] - b);
    }
}

__global__ void k_scatter(const int* __restrict__ src,
                          const int* __restrict__ dst,
                          const float* __restrict__ u_hat,
                          const float* __restrict__ fn,
                          const float* __restrict__ fa,
                          const float* __restrict__ fd,
                          int E) {
    int e = blockIdx.x * blockDim.x + threadIdx.x;
    if (e >= E) return;
    int s = src[e], d = dst[e];
    float area = fa[e];
    float w = area / fmaxf(fd[e], 1e-8f);
    float n0 = fn[e * 3 + 0], n1 = fn[e * 3 + 1], n2 = fn[e * 3 + 2];
    float uf0 = 0.5f * (u_hat[s * 3 + 0] + u_hat[d * 3 + 0]);
    float uf1 = 0.5f * (u_hat[s * 3 + 1] + u_hat[d * 3 + 1]);
    float uf2 = 0.5f * (u_hat[s * 3 + 2] + u_hat[d * 3 + 2]);
    float flux = (uf0 * n0 + uf1 * n1 + uf2 * n2) * area;
    int pos = atomicAdd(&g_cur[d], 1);
    g_ew[pos] = make_int2(s, __float_as_int(w));
    atomicAdd(&g_diag[d], w);
    atomicAdd(&g_divacc[d], flux);
}

// elementwise CG init; seed ap = diag*p0; accumulate rz[0], rr[0]
__global__ void k_rowinit(const float* __restrict__ cv, int N) {
    int i = blockIdx.x * blockDim.x + threadIdx.x;
    double rz = 0.0, rr = 0.0;
    if (i < N) {
        float dgn = g_diag[i];
        float mi = 1.f / fmaxf(dgn, 1e-8f);
        float V = fmaxf(cv[i], 1e-12f);
        float b = g_divacc[i] / V;
        float z = mi * b;
        g_minv[i] = mi;
        g_phi[i] = 0.f;
        g_r[i] = b;
        g_p[i] = z;
        g_ap[i] = dgn * z;           // diag part of A*p0
        rz = (double)b * (double)z;
        rr = (double)b * (double)b;
    }
    double u = blk_reduce_d(rz);
    if (threadIdx.x == 0) atomicAdd(&g_rz[0], u);
    u = blk_reduce_d(rr);
    if (threadIdx.x == 0) atomicAdd(&g_rr[0], u);
}

// ---------------- CG: edge-centric off-diagonal matvec ----------------
__global__ void __launch_bounds__(256) k_edge_mv(int E) {
    int t = blockIdx.x * blockDim.x + threadIdx.x;
    int base = t * EPT;
    if (base >= E) return;
    if (base + EPT <= E) {
        const int4* ew4 = reinterpret_cast<const int4*>(g_ew);
        int t4 = t * 4;
        int4 e0 = ew4[t4 + 0], e1 = ew4[t4 + 1], e2 = ew4[t4 + 2], e3 = ew4[t4 + 3];
        int rbase = g_trow[t];
        uint2 dd = g_rowd2[t];
        // 8 independent gathers
        float q0 = g_p[e0.x], q1 = g_p[e0.z];
        float q2 = g_p[e1.x], q3 = g_p[e1.z];
        float q4 = g_p[e2.x], q5 = g_p[e2.z];
        float q6 = g_p[e3.x], q7 = g_p[e3.z];
        float vals[8];
        vals[0] = __int_as_float(e0.y) * q0;
        vals[1] = __int_as_float(e0.w) * q1;
        vals[2] = __int_as_float(e1.y) * q2;
        vals[3] = __int_as_float(e1.w) * q3;
        vals[4] = __int_as_float(e2.y) * q4;
        vals[5] = __int_as_float(e2.w) * q5;
        vals[6] = __int_as_float(e3.y) * q6;
        vals[7] = __int_as_float(e3.w) * q7;
        int rows[8];
        rows[0] = rbase + ((dd.x      ) & 0xFF);
        rows[1] = rbase + ((dd.x >>  8) & 0xFF);
        rows[2] = rbase + ((dd.x >> 16) & 0xFF);
        rows[3] = rbase + ((dd.x >> 24)       );
        rows[4] = rbase + ((dd.y      ) & 0xFF);
        rows[5] = rbase + ((dd.y >>  8) & 0xFF);
        rows[6] = rbase + ((dd.y >> 16) & 0xFF);
        rows[7] = rbase + ((dd.y >> 24)       );
        float acc = vals[0];
        int cur = rows[0];
        #pragma unroll
        for (int k = 1; k < EPT; k++) {
            if (rows[k] == cur) acc += vals[k];
            else { atomicAdd(&g_ap[cur], -acc); cur = rows[k]; acc = vals[k]; }
        }
        atomicAdd(&g_ap[cur], -acc);
    } else {
        const unsigned char* rb = reinterpret_cast<const unsigned char*>(g_rowd2);
        float acc = 0.f;
        int cur = -1;
        for (int k = base; k < E; k++) {
            int2 ew = g_ew[k];
            int rw = g_trow[k >> 3] + rb[k];
            float v = __int_as_float(ew.y) * g_p[ew.x];
            if (rw == cur) acc += v;
            else { if (cur >= 0) atomicAdd(&g_ap[cur], -acc); cur = rw; acc = v; }
        }
        if (cur >= 0) atomicAdd(&g_ap[cur], -acc);
    }
}

// pAp[it] = sum p_i * ap_i  (ap now complete)
__global__ void k_pap(int N, int it) {
    int i = blockIdx.x * blockDim.x + threadIdx.x;
    double c = 0.0;
    int i4 = i * 4;
    if (i4 + 3 < N) {
        float4 p = *reinterpret_cast<const float4*>(&g_p[i4]);
        float4 a = *reinterpret_cast<const float4*>(&g_ap[i4]);
        c = (double)p.x * a.x + (double)p.y * a.y + (double)p.z * a.z + (double)p.w * a.w;
    } else {
        for (int j = i4; j < N; j++) c += (double)g_p[j] * (double)g_ap[j];
    }
    double u = blk_reduce_d(c);
    if (threadIdx.x == 0) atomicAdd(&g_pap[it], u);
}

// if active: phi += a p; r -= a ap; acc rz_new (r*minv*r), rr_new
__global__ void k_upd_phi_r(int N, int it) {
    int i = blockIdx.x * blockDim.x + threadIdx.x;
    bool act = (g_rr[it] >= TOL2);
    float alpha = (float)(g_rz[it] / (g_pap[it] + 1e-12));
    double rzc = 0.0, rrc = 0.0;
    int i4 = i * 4;
    if (act && i4 < N) {
        if (i4 + 3 < N) {
            float4 p  = *reinterpret_cast<const float4*>(&g_p[i4]);
            float4 ap = *reinterpret_cast<const float4*>(&g_ap[i4]);
            float4 r  = *reinterpret_cast<const float4*>(&g_r[i4]);
            float4 mi = *reinterpret_cast<const float4*>(&g_minv[i4]);
            float4 ph = *reinterpret_cast<const float4*>(&g_phi[i4]);
            ph.x += alpha * p.x; ph.y += alpha * p.y;
            ph.z += alpha * p.z; ph.w += alpha * p.w;
            r.x -= alpha * ap.x; r.y -= alpha * ap.y;
            r.z -= alpha * ap.z; r.w -= alpha * ap.w;
            *reinterpret_cast<float4*>(&g_phi[i4]) = ph;
            *reinterpret_cast<float4*>(&g_r[i4]) = r;
            rzc = (double)r.x * (mi.x * r.x) + (double)r.y * (mi.y * r.y)
                + (double)r.z * (mi.z * r.z) + (double)r.w * (mi.w * r.w);
            rrc = (double)r.x * r.x + (double)r.y * r.y
                + (double)r.z * r.z + (double)r.w * r.w;
        } else {
            for (int j = i4; j < N; j++) {
                g_phi[j] += alpha * g_p[j];
                float rn = g_r[j] - alpha * g_ap[j];
                g_r[j] = rn;
                rzc += (double)rn * (g_minv[j] * rn);
                rrc += (double)rn * rn;
            }
        }
    }
    double u = blk_reduce_d(rzc);
    if (threadIdx.x == 0) atomicAdd(&g_rz[it + 1], u);
    u = blk_reduce_d(rrc);
    if (threadIdx.x == 0) atomicAdd(&g_rr[it + 1], u);
}

// if active: p = minv*r + beta*p; always reseed ap = diag*p (for next matvec)
__global__ void k_upd_p(int N, int it) {
    int i = blockIdx.x * blockDim.x + threadIdx.x;
    int i4 = i * 4;
    if (i4 >= N) return;
    bool act = (g_rr[it] >= TOL2);
    float beta = (float)(g_rz[it + 1] / (g_rz[it] + 1e-12));
    if (i4 + 3 < N) {
        float4 p  = *reinterpret_cast<const float4*>(&g_p[i4]);
        float4 d  = *reinterpret_cast<const float4*>(&g_diag[i4]);
        if (act) {
            float4 r  = *reinterpret_cast<const float4*>(&g_r[i4]);
            float4 mi = *reinterpret_cast<const float4*>(&g_minv[i4]);
            p.x = mi.x * r.x + beta * p.x;
            p.y = mi.y * r.y + beta * p.y;
            p.z = mi.z * r.z + beta * p.z;
            p.w = mi.w * r.w + beta * p.w;
            *reinterpret_cast<float4*>(&g_p[i4]) = p;
        }
        float4 ap;
        ap.x = d.x * p.x; ap.y = d.y * p.y; ap.z = d.z * p.z; ap.w = d.w * p.w;
        *reinterpret_cast<float4*>(&g_ap[i4]) = ap;
    } else {
        for (int j = i4; j < N; j++) {
            float p = g_p[j];
            if (act) { p = g_minv[j] * g_r[j] + beta * p; g_p[j] = p; }
            g_ap[j] = g_diag[j] * p;
        }
    }
}

// ---------------- correction ----------------
__global__ void k_grad(const int* __restrict__ src,
                       const int* __restrict__ dst,
                       const float* __restrict__ fn,
                       const float* __restrict__ fa,
                       const float* __restrict__ fd,
                       int E) {
    int e = blockIdx.x * blockDim.x + threadIdx.x;
    if (e >= E) return;
    int s = src[e], d = dst[e];
    float w = fa[e] / fmaxf(fd[e], 1e-8f);
    float t = w * g_phi[s];
    atomicAdd(&g_grad[d * 3 + 0], t * fn[e * 3 + 0]);
    atomicAdd(&g_grad[d * 3 + 1], t * fn[e * 3 + 1]);
    atomicAdd(&g_grad[d * 3 + 2], t * fn[e * 3 + 2]);
}

__global__ void k_final(const float* __restrict__ u_hat,
                        const float* __restrict__ cv,
                        float* __restrict__ out, int N) {
    int i = blockIdx.x * blockDim.x + threadIdx.x;
    if (i >= N) return;
    float Vi = 1.f / fmaxf(cv[i], 1e-12f);
    out[i * 3 + 0] = u_hat[i * 3 + 0] - g_grad[i * 3 + 0] * Vi;
    out[i * 3 + 1] = u_hat[i * 3 + 1] - g_grad[i * 3 + 1] * Vi;
    out[i * 3 + 2] = u_hat[i * 3 + 2] - g_grad[i * 3 + 2] * Vi;
    out[3 * N + i] = g_phi[i];
}

// ---------------- launch ----------------
extern "C" void kernel_launch(void* const* d_in, const int* in_sizes, int n_in,
                              void* d_out, int out_size) {
    const float* u_hat = (const float*)d_in[0];
    const int*   ei    = (const int*)  d_in[1];
    const float* fn    = (const float*)d_in[2];
    const float* fa    = (const float*)d_in[3];
    const float* fd    = (const float*)d_in[4];
    const float* cv    = (const float*)d_in[5];
    float* out = (float*)d_out;

    int N = in_sizes[5];
    int E = in_sizes[3];
    const int* src = ei;
    const int* dst = ei + E;

    const int B = 256;
    int gridE   = (E + B - 1) / B;
    int gridN   = (N + B - 1) / B;
    int grid3N  = (3 * N + B - 1) / B;
    int gridMV  = ((E + EPT - 1) / EPT + B - 1) / B;
    int gridN4  = ((N + 3) / 4 + B - 1) / B;
    int nScanBlocks = (N + SCAN_B - 1) / SCAN_B;

    k_zero<<<grid3N, B>>>(N);
    k_hist<<<gridE, B>>>(dst, E);
    k_scan1<<<nScanBlocks, SCAN_B>>>(N);
    k_scan2<<<1, SCAN_B>>>(nScanBlocks);
    k_scan3<<<gridN, B>>>(N, E);
    k_fillrow<<<gridN, B>>>(N);
    k_packrow<<<gridMV, B>>>(E);
    k_scatter<<<gridE, B>>>(src, dst, u_hat, fn, fa, fd, E);
    k_rowinit<<<gridN, B>>>(cv, N);

    for (int it = 0; it < CG_ITERS; ++it) {
        k_edge_mv<<<gridMV, B>>>(E);
        k_pap<<<gridN4, B>>>(N, it);
        k_upd_phi_r<<<gridN4, B>>>(N, it);
        k_upd_p<<<gridN4, B>>>(N, it);
    }

    k_grad<<<gridE, B>>>(src, dst, fn, fa, fd, E);
    k_final<<<gridN, B>>>(u_hat, cv, out, N);
}